// round 4
// baseline (speedup 1.0000x reference)
#include <cuda_runtime.h>
#include <stdint.h>

// StridedSlice: out[n,c,h,w] = x[n,c,2h,2w]
//   in : (8,128,512,512) f32   in row = 128 float4, plane = 65536 float4
//   out: (8,128,256,256) f32   out row = 64 float4, 262144 rows total
//
// One warp produces 2 consecutive output rows (128 float4 = 2 KB) from
// 2 even input rows (4 KB). Thread t writes out float4 {t,32+t,64+t,96+t}
// (fully coalesced STG.128). Each output float4 consumes one aligned 32 B
// input sector, loaded with a single 256-bit load (ld.global.cs.v8.f32,
// sm_100a+): lane stride 32 B -> each LDG.256 warp instruction covers a
// fully-consumed contiguous 1 KB span. 4 front-batched LDG.256 per thread.

__device__ __forceinline__ void ldg256_cs(const float4* __restrict__ p,
                                          float4& v0, float4& v1)
{
    asm volatile("ld.global.cs.v8.f32 {%0,%1,%2,%3,%4,%5,%6,%7}, [%8];"
                 : "=f"(v0.x), "=f"(v0.y), "=f"(v0.z), "=f"(v0.w),
                   "=f"(v1.x), "=f"(v1.y), "=f"(v1.z), "=f"(v1.w)
                 : "l"(p));
}

__global__ __launch_bounds__(256) void strided_slice_kernel(
    const float4* __restrict__ in, float4* __restrict__ out)
{
    unsigned wg = (blockIdx.x * 256u + threadIdx.x) >> 5;  // global warp id
    unsigned t  = threadIdx.x & 31u;

    unsigned r0 = wg << 1;          // first of 2 output rows for this warp
    unsigned h  = r0 & 255u;        // even; both rows stay in one plane
    unsigned nc = r0 >> 8;

    const float4* __restrict__ ib = in + ((size_t)nc << 16) + ((size_t)h << 8);
    float4* __restrict__ ob = out + ((size_t)r0 << 6);

    unsigned t2 = t << 1;

    // 4 front-batched 256-bit streaming loads (each = one aligned 32 B sector/lane)
    float4 a0, a1, a2, a3, b0, b1, b2, b3;
    ldg256_cs(ib + t2,       a0, a1);   // row 2h,   cols 0..31 of out row
    ldg256_cs(ib + t2 + 64,  a2, a3);   // row 2h,   cols 32..63
    ldg256_cs(ib + t2 + 256, b0, b1);   // row 2h+2, cols 0..31
    ldg256_cs(ib + t2 + 320, b2, b3);   // row 2h+2, cols 32..63

    __stcs(ob + t,      make_float4(a0.x, a0.z, a1.x, a1.z));
    __stcs(ob + 32 + t, make_float4(a2.x, a2.z, a3.x, a3.z));
    __stcs(ob + 64 + t, make_float4(b0.x, b0.z, b1.x, b1.z));
    __stcs(ob + 96 + t, make_float4(b2.x, b2.z, b3.x, b3.z));
}

extern "C" void kernel_launch(void* const* d_in, const int* in_sizes, int n_in,
                              void* d_out, int out_size)
{
    (void)in_sizes; (void)n_in; (void)out_size;
    const float4* in  = (const float4*)d_in[0];
    float4*       out = (float4*)d_out;

    // 262144 output rows / 2 rows per warp = 131072 warps = 16384 blocks of 256
    strided_slice_kernel<<<16384, 256>>>(in, out);
}